// round 4
// baseline (speedup 1.0000x reference)
#include <cuda_runtime.h>

#define BS 64
#define NUM_ACTION 125
#define NUM_NOUN 352
#define NUM_CLS (NUM_ACTION + NUM_NOUN)   // 477
#define DD 5
#define HW 1024                            // 32*32
#define CH_TOTAL ((64 + NUM_ACTION + NUM_NOUN) * DD)  // 2705
#define CONF_BASE (63 * DD)                // channel 63 -> pred channels 315..319
#define NTH 512
#define NWARP (NTH / 32)                   // 16
#define NEG_INF (-__int_as_float(0x7f800000))

__device__ float g_losses[BS * 2];
__device__ unsigned int g_done = 0;

__device__ __forceinline__ void amax_upd(float v, int s, float& bv, int& bs_) {
    if (v > bv || (v == bv && s < bs_)) { bv = v; bs_ = s; }
}

__global__ void __launch_bounds__(NTH) fused_kernel(
    const float* __restrict__ pred,
    const int* __restrict__ action_gt,
    const int* __restrict__ noun_gt,
    float* __restrict__ out)
{
    const int b    = blockIdx.x;
    const int t    = threadIdx.x;
    const int lane = t & 31;
    const int wid  = t >> 5;
    const float* base = pred + (size_t)b * CH_TOTAL * HW;
    const float4* conf4 = (const float4*)(base + (size_t)CONF_BASE * HW); // 1280 float4

    __shared__ float wval[NWARP];
    __shared__ int   widx[NWARP];
    __shared__ float wmax[NWARP];
    __shared__ float wsum[NWARP];
    __shared__ float ch[NUM_CLS];

    // ---- Phase 1: argmax over s = hw*5 + d (first-max tie-break) ----
    float bv = NEG_INF;
    int   bsi = 0x7fffffff;
    for (int i4 = t; i4 < 1280; i4 += NTH) {
        float4 v = conf4[i4];
        int j = i4 * 4;
        int d = j >> 10, hw = j & 1023;   // no d-boundary inside a float4
        amax_upd(v.x, (hw + 0) * DD + d, bv, bsi);
        amax_upd(v.y, (hw + 1) * DD + d, bv, bsi);
        amax_upd(v.z, (hw + 2) * DD + d, bv, bsi);
        amax_upd(v.w, (hw + 3) * DD + d, bv, bsi);
    }
    #pragma unroll
    for (int off = 16; off > 0; off >>= 1) {
        float ov = __shfl_down_sync(0xffffffff, bv, off);
        int   os = __shfl_down_sync(0xffffffff, bsi, off);
        amax_upd(ov, os, bv, bsi);
    }
    if (lane == 0) { wval[wid] = bv; widx[wid] = bsi; }
    __syncthreads();                                   // #1

    // every thread reduces the 16 partials locally (no broadcast barrier)
    float fv = wval[0]; int top = widx[0];
    #pragma unroll
    for (int w = 1; w < NWARP; w++) amax_upd(wval[w], widx[w], fv, top);
    const int d  = top % DD;
    const int hw = top / DD;

    // ---- Phase 2: gather 477 chosen logits (1 load/thread) ----
    if (t < NUM_CLS)
        ch[t] = base[(size_t)((64 + t) * DD + d) * HW + hw];
    __syncthreads();                                   // #2

    // ---- Phase 3: both logsumexps in parallel (warps 0-3 action, 4-15 noun) ----
    const bool is_action = (t < 128);
    const int  c     = is_action ? t : (t - 128);
    const bool valid = c < (is_action ? NUM_ACTION : NUM_NOUN);
    const float x = valid ? ch[is_action ? c : (NUM_ACTION + c)] : NEG_INF;

    float m = x;
    #pragma unroll
    for (int off = 16; off > 0; off >>= 1)
        m = fmaxf(m, __shfl_down_sync(0xffffffff, m, off));
    if (lane == 0) wmax[wid] = m;
    __syncthreads();                                   // #3

    float gmax;
    if (is_action) {
        gmax = fmaxf(fmaxf(wmax[0], wmax[1]), fmaxf(wmax[2], wmax[3]));
    } else {
        gmax = wmax[4];
        #pragma unroll
        for (int w = 5; w < NWARP; w++) gmax = fmaxf(gmax, wmax[w]);
    }

    float e = valid ? __expf(x - gmax) : 0.f;
    #pragma unroll
    for (int off = 16; off > 0; off >>= 1)
        e += __shfl_down_sync(0xffffffff, e, off);
    if (lane == 0) wsum[wid] = e;
    __syncthreads();                                   // #4

    if (t == 0) {
        float sa = wsum[0] + wsum[1] + wsum[2] + wsum[3];
        float sn = wsum[4];
        #pragma unroll
        for (int w = 5; w < NWARP; w++) sn += wsum[w];
        float amax = gmax;  // t==0 is in the action group
        float nmax = wmax[4];
        #pragma unroll
        for (int w = 5; w < NWARP; w++) nmax = fmaxf(nmax, wmax[w]);
        float lse_a = amax + __logf(sa);
        float lse_n = nmax + __logf(sn);
        g_losses[b * 2 + 0] = lse_a - ch[action_gt[b]];
        g_losses[b * 2 + 1] = lse_n - ch[NUM_ACTION + noun_gt[b]];
        __threadfence();   // release g_losses before the done-count atomic
    }

    // ---- tail: warp 0 only, no block barriers ----
    if (wid != 0) return;
    unsigned int cnt = 0;
    if (lane == 0) cnt = atomicAdd(&g_done, 1u);
    cnt = __shfl_sync(0xffffffff, cnt, 0);
    if (cnt != BS - 1) return;

    __threadfence();       // acquire: see all CTAs' g_losses
    volatile float* gl = (volatile float*)g_losses;
    float sa = gl[lane * 2 + 0] + gl[(lane + 32) * 2 + 0];
    float sn = gl[lane * 2 + 1] + gl[(lane + 32) * 2 + 1];
    #pragma unroll
    for (int off = 16; off > 0; off >>= 1) {
        sa += __shfl_down_sync(0xffffffff, sa, off);
        sn += __shfl_down_sync(0xffffffff, sn, off);
    }
    if (lane == 0) {
        const float la = sa * 0.5f;
        const float ln = sn * 0.5f;
        out[0] = la + ln;
        out[1] = la;
        out[2] = ln;
        g_done = 0;        // reset for next graph replay
    }
}

extern "C" void kernel_launch(void* const* d_in, const int* in_sizes, int n_in,
                              void* d_out, int out_size)
{
    const float* pred = (const float*)d_in[0];
    const int*   ag   = (const int*)d_in[1];
    const int*   ng   = (const int*)d_in[2];
    float* out = (float*)d_out;

    fused_kernel<<<BS, NTH>>>(pred, ag, ng, out);
}

// round 5
// speedup vs baseline: 1.0332x; 1.0332x over previous
#include <cuda_runtime.h>

#define BS 64
#define NUM_ACTION 125
#define NUM_NOUN 352
#define NUM_CLS (NUM_ACTION + NUM_NOUN)   // 477
#define DD 5
#define HW 1024                            // 32*32
#define CH_TOTAL ((64 + NUM_ACTION + NUM_NOUN) * DD)  // 2705
#define CONF_BASE (63 * DD)                // channel 63 -> pred channels 315..319
#define NTH 256
#define NWARP (NTH / 32)                   // 8
#define NEG_INF (-__int_as_float(0x7f800000))

__device__ float2 g_losses[BS];
__device__ unsigned int g_done = 0;

__device__ __forceinline__ void amax_upd(float v, int s, float& bv, int& bs_) {
    if (v > bv || (v == bv && s < bs_)) { bv = v; bs_ = s; }
}

__global__ void __launch_bounds__(NTH) fused_kernel(
    const float* __restrict__ pred,
    const int* __restrict__ action_gt,
    const int* __restrict__ noun_gt,
    float* __restrict__ out)
{
    const int b    = blockIdx.x;
    const int t    = threadIdx.x;
    const int lane = t & 31;
    const int wid  = t >> 5;
    const float* base = pred + (size_t)b * CH_TOTAL * HW;
    const float4* conf4 = (const float4*)(base + (size_t)CONF_BASE * HW); // 1280 float4

    __shared__ float wval[NWARP];
    __shared__ int   widx[NWARP];
    __shared__ float wmax[NWARP];
    __shared__ float wsum[NWARP];
    __shared__ float ch[NUM_CLS];

    // ---- Phase 1: argmax over s = hw*5 + d (first-max tie-break), 5 f4/thread ----
    float bv = NEG_INF;
    int   bsi = 0x7fffffff;
    #pragma unroll
    for (int k = 0; k < 5; k++) {
        int i4 = t + k * NTH;               // < 1280
        float4 v = conf4[i4];
        int j = i4 * 4;
        int d = j >> 10, hw = j & 1023;     // no d-boundary inside a float4
        amax_upd(v.x, (hw + 0) * DD + d, bv, bsi);
        amax_upd(v.y, (hw + 1) * DD + d, bv, bsi);
        amax_upd(v.z, (hw + 2) * DD + d, bv, bsi);
        amax_upd(v.w, (hw + 3) * DD + d, bv, bsi);
    }
    #pragma unroll
    for (int off = 16; off > 0; off >>= 1) {
        float ov = __shfl_down_sync(0xffffffff, bv, off);
        int   os = __shfl_down_sync(0xffffffff, bsi, off);
        amax_upd(ov, os, bv, bsi);
    }
    if (lane == 0) { wval[wid] = bv; widx[wid] = bsi; }
    __syncthreads();                                   // #1

    // replicated combine (no broadcast barrier)
    float fv = wval[0]; int top = widx[0];
    #pragma unroll
    for (int w = 1; w < NWARP; w++) amax_upd(wval[w], widx[w], fv, top);
    const int d  = top % DD;
    const int hw = top / DD;

    // ---- Phase 2: gather 477 chosen logits (<=2 loads/thread) ----
    const float* gbase = base + (size_t)(64 * DD + d) * HW + hw;
    ch[t] = gbase[(size_t)t * DD * HW];
    if (t < NUM_CLS - NTH)
        ch[t + NTH] = gbase[(size_t)(t + NTH) * DD * HW];
    __syncthreads();                                   // #2

    // ---- Phase 3: parallel logsumexp (warps 0-3 action, 4-7 noun) ----
    const bool is_action = (t < 128);
    float x0 = NEG_INF, x1 = NEG_INF, x2 = NEG_INF;
    if (is_action) {
        if (t < NUM_ACTION) x0 = ch[t];
    } else {
        const int nt = t - 128;             // 0..127; 352 = 128+128+96
        x0 = ch[NUM_ACTION + nt];
        x1 = ch[NUM_ACTION + nt + 128];
        if (nt < 96) x2 = ch[NUM_ACTION + nt + 256];
    }
    float m = fmaxf(fmaxf(x0, x1), x2);
    #pragma unroll
    for (int off = 16; off > 0; off >>= 1)
        m = fmaxf(m, __shfl_down_sync(0xffffffff, m, off));
    if (lane == 0) wmax[wid] = m;
    __syncthreads();                                   // #3

    float gmax;
    if (is_action)
        gmax = fmaxf(fmaxf(wmax[0], wmax[1]), fmaxf(wmax[2], wmax[3]));
    else
        gmax = fmaxf(fmaxf(wmax[4], wmax[5]), fmaxf(wmax[6], wmax[7]));

    float e = (x0 > NEG_INF) ? __expf(x0 - gmax) : 0.f;
    if (x1 > NEG_INF) e += __expf(x1 - gmax);
    if (x2 > NEG_INF) e += __expf(x2 - gmax);
    #pragma unroll
    for (int off = 16; off > 0; off >>= 1)
        e += __shfl_down_sync(0xffffffff, e, off);
    if (lane == 0) wsum[wid] = e;
    __syncthreads();                                   // #4

    if (t == 0) {
        const float amax = gmax;   // t==0 belongs to the action group
        const float nmax = fmaxf(fmaxf(wmax[4], wmax[5]), fmaxf(wmax[6], wmax[7]));
        const float sa = (wsum[0] + wsum[1]) + (wsum[2] + wsum[3]);
        const float sn = (wsum[4] + wsum[5]) + (wsum[6] + wsum[7]);
        const float lse_a = amax + __logf(sa);
        const float lse_n = nmax + __logf(sn);
        float2 lp;
        lp.x = lse_a - ch[action_gt[b]];
        lp.y = lse_n - ch[NUM_ACTION + noun_gt[b]];
        g_losses[b] = lp;
        __threadfence();           // release before done-count
    }

    // ---- tail: warp 0 only, no block barriers ----
    if (wid != 0) return;
    unsigned int cnt = 0;
    if (lane == 0) cnt = atomicAdd(&g_done, 1u);
    cnt = __shfl_sync(0xffffffff, cnt, 0);
    if (cnt != BS - 1) return;

    __threadfence();               // acquire: see all CTAs' g_losses
    volatile float2* gl = (volatile float2*)g_losses;
    float2 p0, p1;
    p0.x = gl[lane].x;      p0.y = gl[lane].y;
    p1.x = gl[lane + 32].x; p1.y = gl[lane + 32].y;
    float sa = p0.x + p1.x;
    float sn = p0.y + p1.y;
    #pragma unroll
    for (int off = 16; off > 0; off >>= 1) {
        sa += __shfl_down_sync(0xffffffff, sa, off);
        sn += __shfl_down_sync(0xffffffff, sn, off);
    }
    if (lane == 0) {
        const float la = sa * 0.5f;
        const float ln = sn * 0.5f;
        out[0] = la + ln;
        out[1] = la;
        out[2] = ln;
        g_done = 0;                // reset for next graph replay
    }
}

extern "C" void kernel_launch(void* const* d_in, const int* in_sizes, int n_in,
                              void* d_out, int out_size)
{
    const float* pred = (const float*)d_in[0];
    const int*   ag   = (const int*)d_in[1];
    const int*   ng   = (const int*)d_in[2];
    float* out = (float*)d_out;

    fused_kernel<<<BS, NTH>>>(pred, ag, ng, out);
}